// round 10
// baseline (speedup 1.0000x reference)
#include <cuda_runtime.h>

#define T_LEN   2048
#define CSTEP   16                      // timesteps per chunk
#define NCHUNK  (T_LEN / CSTEP)         // 128
#define NITER   (NCHUNK + 3)            // 4-deep pipeline: L -> A -> B -> C
#define NGRP_C  (CSTEP / 4)             // float4-groups per chunk (4)

// tanh via EX2+RCP: tanh(a) = 1 - 2/(e^{2a}+1),  e^{2a} = 2^{a*2.885390}.
// MUFU.TANH measures ~40 cyc/warp throughput on this part; EX2 and RCP are
// rt-8 MUFUs, so this halves+ the binding MUFU pressure. Saturation exact:
// a >> 0: ex2 -> inf, rcp -> 0, t = 1;  a << 0: ex2 -> 0, rcp(1) = 1, t = -1.
__device__ __forceinline__ float tanh_fast(float a) {
    float e, r;
    asm("ex2.approx.f32 %0, %1;" : "=f"(e) : "f"(a * 2.8853900817779268f));
    asm("rcp.approx.f32 %0, %1;" : "=f"(r) : "f"(e + 1.0f));
    return fmaf(-2.0f, r, 1.0f);
}

// State in the x10 domain (WU = 10*wu etc); clips at +-1e5 are exact no-ops
// on reachable values (|state| <= O(T) ~ 2e3).
//
// 4-warp pipeline, skewed by one chunk per stage (structure of the R6 winner):
//   warp3 (L): STS chunk k (preloaded into regs at iter k-1), LDG chunk k+1
//   warp0 (A): WU chain  on chunk k-1 -> REM, D1, ct2 = p - c2*(wu/W)^2
//   warp1 (B): WL chain  on chunk k-2 -> X, D2
//   warp2 (C): WD chain  on chunk k-3 -> q, global stores
__global__ void __launch_bounds__(128, 1) xaj_kernel(
    const float* __restrict__ inputs,
    const float* __restrict__ pwum, const float* __restrict__ pwlm,
    const float* __restrict__ pwdm, const float* __restrict__ pc,
    const float* __restrict__ pb,  const float* __restrict__ pk1,
    const float* __restrict__ pk2, const float* __restrict__ pk3,
    float* __restrict__ out, int B)
{
    __shared__ float sPET[2][CSTEP][32];
    __shared__ float sP  [2][CSTEP][32];
    __shared__ float sREM[2][CSTEP][32];
    __shared__ float sD1 [2][CSTEP][32];
    __shared__ float sX  [2][CSTEP][32];
    __shared__ float sD2 [2][CSTEP][32];
    __shared__ float sCT [3][CSTEP][32];   // ct2 travels A -> C (distance 2)

    const int lane = threadIdx.x & 31;
    const int wid  = threadIdx.x >> 5;
    const int row  = blockIdx.x * 32 + lane;

    // scalar params (reference arg swap: runoff_production(wu, wd, wl, p,
    // wum, wdm, wlm, b, c))
    const float wum_p = pwum[0] * 19.9f + 0.1f;
    const float wlm_p = pwdm[0] * 30.0f + 60.0f;
    const float wdm_p = pwlm[0] * 60.0f + 60.0f;
    const float W      = wum_p + wlm_p + wdm_p;
    const float invW10 = 0.1f / W;           // x10-state -> w/W
    const float negc2  = -(pc[0] * 0.19f + 0.01f);
    const float negb2  = -(pb[0] * 0.30f + 0.10f);
    const float k1 = pk1[0] * 0.69f + 0.01f;
    const float k2 = pk2[0] * 0.69f + 0.01f;
    const float k3 = pk3[0] * 0.89f + 0.01f;
    const float F  = k1 + 0.5f * k2 * (1.0f - k1)
                   + 0.25f * k3 * (1.0f - k2) * (1.0f - k1);
    const float halfF = 0.5f * F;

    const float4* __restrict__ in4 =
        reinterpret_cast<const float4*>(inputs + (size_t)row * (T_LEN * 3));
    float4* __restrict__ out4 =
        reinterpret_cast<float4*>(out + (size_t)row * T_LEN);

    float WU = 0.0f, WL = 0.0f, WD = 0.0f;

    // loader's in-flight chunk registers (chunk to be STS'd this iteration)
    float4 f[NGRP_C][3];
    if (wid == 3) {
        #pragma unroll
        for (int j = 0; j < NGRP_C; ++j) {
            f[j][0] = in4[j * 3 + 0];
            f[j][1] = in4[j * 3 + 1];
            f[j][2] = in4[j * 3 + 2];
        }
    }

    for (int k = 0; k < NITER; ++k) {
        if (wid == 3) {
            // ---- loader: STS chunk k, then issue LDGs for chunk k+1 ----
            if (k < NCHUNK) {
                const int slot = k & 1;
                #pragma unroll
                for (int j = 0; j < NGRP_C; ++j) {
                    // (B,T,3): pet = ch0, p = ch2
                    const float pet_[4] = { f[j][0].x, f[j][0].w,
                                            f[j][1].z, f[j][2].y };
                    const float pr_ [4] = { f[j][0].z, f[j][1].y,
                                            f[j][2].x, f[j][2].w };
                    #pragma unroll
                    for (int i = 0; i < 4; ++i) {
                        sPET[slot][j * 4 + i][lane] = 10.0f * pet_[i];
                        sP  [slot][j * 4 + i][lane] = 10.0f * pr_[i];
                    }
                }
                if (k + 1 < NCHUNK) {
                    #pragma unroll
                    for (int j = 0; j < NGRP_C; ++j) {
                        const int g = (k + 1) * NGRP_C + j;
                        f[j][0] = in4[g * 3 + 0];
                        f[j][1] = in4[g * 3 + 1];
                        f[j][2] = in4[g * 3 + 2];
                    }
                }
            }
        } else if (wid == 0) {
            // ---- stage A: WU chain, chunk k-1 ----
            if (k >= 1 && k <= NCHUNK) {
                const int ka = k - 1, slot = ka & 1, cslot = ka % 3;
                #pragma unroll 4
                for (int t = 0; t < CSTEP; ++t) {
                    const float pet10 = sPET[slot][t][lane];
                    const float p10   = sP  [slot][t][lane];
                    const float a    = WU - pet10;
                    const float ha   = 0.5f * a;
                    const float ct   = fmaf(-0.5f, pet10, p10);
                    const float base = fmaf(0.5f, WU, ct);
                    const float sum  = WU + p10;
                    const float t1   = tanh_fast(a);
                    const float WUn  = fmaf(t1, ha, base);   // carried chain
                    const float ET1  = sum - WUn;            // off-chain
                    const float Z    = pet10 - ET1;
                    const float tr   = tanh_fast(Z);
                    const float hZ   = 0.5f * Z;
                    const float REM  = fmaf(tr, hZ, hZ);
                    const float D1   = p10 - ET1;
                    const float u    = WUn * invW10;         // wu/W (new state)
                    const float cu   = negc2 * u;
                    const float praw = 0.1f * p10;
                    const float ct2  = fmaf(cu, u, praw);    // p - c2*u^2
                    sREM[slot][t][lane]  = REM;
                    sD1 [slot][t][lane]  = D1;
                    sCT [cslot][t][lane] = ct2;
                    WU = WUn;
                }
            }
        } else if (wid == 1) {
            // ---- stage B: WL chain, chunk k-2 ----
            if (k >= 2 && k <= NCHUNK + 1) {
                const int kb = k - 2, slot = kb & 1;
                #pragma unroll 4
                for (int t = 0; t < CSTEP; ++t) {
                    const float REM  = sREM[slot][t][lane];
                    const float D1   = sD1 [slot][t][lane];
                    const float t3   = tanh_fast(REM);           // gate H(rem)
                    const float g3   = fmaf(t3,  0.5f,  0.5f);
                    const float ng3  = fmaf(t3, -0.5f, -0.5f);
                    const float aB   = REM - WL;
                    const float t2   = tanh_fast(aB);
                    const float hB   = -0.5f * aB;               // 0.5(WL-REM)
                    const float mB   = fmaf(0.5f, WL, 0.5f * REM);
                    const float ET22 = fmaf(t2, hB, mB);         // carried chain
                    const float ET2  = g3 * ET22;
                    const float WLD  = WL + D1;
                    WL = fmaf(ng3, ET22, WLD);                   // WL + D1 - ET2
                    sX [slot][t][lane] = REM - ET2;
                    sD2[slot][t][lane] = D1  - ET2;
                }
            }
        } else {
            // ---- stage C: WD chain + runoff/q, chunk k-3 ----
            if (k >= 3) {
                const int kc = k - 3, slot = kc & 1, cslot = kc % 3;
                #pragma unroll
                for (int j = 0; j < NGRP_C; ++j) {
                    float qv[4];
                    #pragma unroll
                    for (int i = 0; i < 4; ++i) {
                        const int   t    = j * 4 + i;
                        const float X    = sX [slot][t][lane];
                        const float D2   = sD2[slot][t][lane];
                        const float ct2  = sCT[cslot][t][lane];
                        const float t5   = tanh_fast(X);         // gate H(x)
                        const float ng5  = fmaf(t5, -0.5f, -0.5f);
                        const float aC   = X - WD;
                        const float t4   = tanh_fast(aC);
                        const float hC   = -0.5f * aC;           // 0.5(WD-X)
                        const float mC   = fmaf(0.5f, WD, 0.5f * X);
                        const float ET33 = fmaf(t4, hC, mC);     // carried chain
                        const float WDD  = WD + D2;
                        const float WDn  = fmaf(ng5, ET33, WDD); // WD + D2 - ET3
                        const float v    = WDn * invW10;         // wd/W (new)
                        const float bv   = negb2 * v;
                        const float dd   = fmaf(bv, v, ct2);     // p - s
                        const float tq   = tanh_fast(10.0f * dd);
                        const float qh   = halfF * dd;
                        qv[i] = fmaf(tq, qh, qh);                // F*H(p-s)*(p-s)
                        WD = WDn;
                    }
                    out4[kc * NGRP_C + j] =
                        make_float4(qv[0], qv[1], qv[2], qv[3]);
                }
            }
        }
        __syncthreads();
    }
}

extern "C" void kernel_launch(void* const* d_in, const int* in_sizes, int n_in,
                              void* d_out, int out_size) {
    const float* inputs = (const float*)d_in[0];
    const float* wum = (const float*)d_in[1];
    const float* wlm = (const float*)d_in[2];
    const float* wdm = (const float*)d_in[3];
    const float* c   = (const float*)d_in[4];
    const float* bb  = (const float*)d_in[5];
    const float* k1  = (const float*)d_in[6];
    const float* k2  = (const float*)d_in[7];
    const float* k3  = (const float*)d_in[8];
    float* out = (float*)d_out;

    const int B = in_sizes[0] / (T_LEN * 3);

    dim3 block(128);                // 4 warps: A, B, C, Loader
    dim3 grid(B / 32);              // 32 rows per block
    xaj_kernel<<<grid, block>>>(inputs, wum, wlm, wdm, c, bb, k1, k2, k3, out, B);
}

// round 12
// speedup vs baseline: 1.8464x; 1.8464x over previous
#include <cuda_runtime.h>

#define T_LEN   2048
#define CSTEP   16                      // timesteps per chunk
#define NCHUNK  (T_LEN / CSTEP)         // 128
#define NITER   (NCHUNK + 4)            // 5-deep pipeline: L->A->B->C->D
#define NGRP_C  (CSTEP / 4)             // float4-groups per chunk (4)

__device__ __forceinline__ float tanh_fast(float x) {
    float y;
    asm("tanh.approx.f32 %0, %1;" : "=f"(y) : "f"(x));
    return y;
}

// State in the x10 domain (WU = 10*wu etc); clips at +-1e5 are exact no-ops.
//
// Empirical law on this part: warp time ~ 40 cyc per MUFU op, independent of
// scheduling. So the pipeline is balanced to <= 2 MUFU per warp per step:
//   warp4 (L): STS chunk k inputs, LDG chunk k+1          (0 MUFU)
//   warp0 (A): WU chain, chunk k-1:  t1, tr               (2 MUFU)
//   warp1 (B): WL chain, chunk k-2:  t3, t2               (2 MUFU)
//   warp2 (C): WD chain, chunk k-3:  t5, t4               (2 MUFU)
//   warp3 (D): runoff/q, chunk k-4:  tq  + global stores  (1 MUFU)
// One __syncthreads per iteration; smem slot counts = producer/consumer
// iteration distance + 1 (sCT: A->D distance 3 -> 4 slots).
__global__ void __launch_bounds__(160, 1) xaj_kernel(
    const float* __restrict__ inputs,
    const float* __restrict__ pwum, const float* __restrict__ pwlm,
    const float* __restrict__ pwdm, const float* __restrict__ pc,
    const float* __restrict__ pb,  const float* __restrict__ pk1,
    const float* __restrict__ pk2, const float* __restrict__ pk3,
    float* __restrict__ out, int B)
{
    __shared__ float2 sPP[2][CSTEP][32];   // (pet10, p10)  L -> A
    __shared__ float2 sRD[2][CSTEP][32];   // (REM, D1)     A -> B
    __shared__ float2 sXD[2][CSTEP][32];   // (X, D2)       B -> C
    __shared__ float  sWD[2][CSTEP][32];   // WDn           C -> D
    __shared__ float  sCT[4][CSTEP][32];   // ct2           A -> D (distance 3)

    const int lane = threadIdx.x & 31;
    const int wid  = threadIdx.x >> 5;
    const int row  = blockIdx.x * 32 + lane;

    // scalar params (reference arg swap: runoff_production(wu, wd, wl, p,
    // wum, wdm, wlm, b, c))
    const float wum_p = pwum[0] * 19.9f + 0.1f;
    const float wlm_p = pwdm[0] * 30.0f + 60.0f;
    const float wdm_p = pwlm[0] * 60.0f + 60.0f;
    const float W      = wum_p + wlm_p + wdm_p;
    const float invW10 = 0.1f / W;           // x10-state -> w/W
    const float negc2  = -(pc[0] * 0.19f + 0.01f);
    const float negb2  = -(pb[0] * 0.30f + 0.10f);
    const float k1 = pk1[0] * 0.69f + 0.01f;
    const float k2 = pk2[0] * 0.69f + 0.01f;
    const float k3 = pk3[0] * 0.89f + 0.01f;
    const float F  = k1 + 0.5f * k2 * (1.0f - k1)
                   + 0.25f * k3 * (1.0f - k2) * (1.0f - k1);
    const float halfF = 0.5f * F;

    const float4* __restrict__ in4 =
        reinterpret_cast<const float4*>(inputs + (size_t)row * (T_LEN * 3));
    float4* __restrict__ out4 =
        reinterpret_cast<float4*>(out + (size_t)row * T_LEN);

    float WU = 0.0f, WL = 0.0f, WD = 0.0f;

    // loader's in-flight chunk registers (chunk to be STS'd this iteration)
    float4 f[NGRP_C][3];
    if (wid == 4) {
        #pragma unroll
        for (int j = 0; j < NGRP_C; ++j) {
            f[j][0] = in4[j * 3 + 0];
            f[j][1] = in4[j * 3 + 1];
            f[j][2] = in4[j * 3 + 2];
        }
    }

    for (int k = 0; k < NITER; ++k) {
        if (wid == 4) {
            // ---- loader: STS chunk k, then issue LDGs for chunk k+1 ----
            if (k < NCHUNK) {
                const int slot = k & 1;
                #pragma unroll
                for (int j = 0; j < NGRP_C; ++j) {
                    // (B,T,3): pet = ch0, p = ch2
                    const float pet_[4] = { f[j][0].x, f[j][0].w,
                                            f[j][1].z, f[j][2].y };
                    const float pr_ [4] = { f[j][0].z, f[j][1].y,
                                            f[j][2].x, f[j][2].w };
                    #pragma unroll
                    for (int i = 0; i < 4; ++i)
                        sPP[slot][j * 4 + i][lane] =
                            make_float2(10.0f * pet_[i], 10.0f * pr_[i]);
                }
                if (k + 1 < NCHUNK) {
                    #pragma unroll
                    for (int j = 0; j < NGRP_C; ++j) {
                        const int g = (k + 1) * NGRP_C + j;
                        f[j][0] = in4[g * 3 + 0];
                        f[j][1] = in4[g * 3 + 1];
                        f[j][2] = in4[g * 3 + 2];
                    }
                }
            }
        } else if (wid == 0) {
            // ---- stage A: WU chain, chunk k-1 (t1, tr) ----
            if (k >= 1 && k <= NCHUNK) {
                const int ka = k - 1, slot = ka & 1, cslot = ka & 3;
                #pragma unroll 4
                for (int t = 0; t < CSTEP; ++t) {
                    const float2 pp   = sPP[slot][t][lane];
                    const float pet10 = pp.x;
                    const float p10   = pp.y;
                    const float a    = WU - pet10;
                    const float ha   = 0.5f * a;
                    const float ct   = fmaf(-0.5f, pet10, p10);
                    const float base = fmaf(0.5f, WU, ct);
                    const float sum  = WU + p10;
                    const float t1   = tanh_fast(a);
                    const float WUn  = fmaf(t1, ha, base);   // carried chain
                    const float ET1  = sum - WUn;            // off-chain
                    const float Z    = pet10 - ET1;
                    const float tr   = tanh_fast(Z);
                    const float hZ   = 0.5f * Z;
                    const float REM  = fmaf(tr, hZ, hZ);
                    const float D1   = p10 - ET1;
                    const float u    = WUn * invW10;         // wu/W (new state)
                    const float cu   = negc2 * u;
                    const float praw = 0.1f * p10;
                    const float ct2  = fmaf(cu, u, praw);    // p - c2*u^2
                    sRD[slot][t][lane]  = make_float2(REM, D1);
                    sCT[cslot][t][lane] = ct2;
                    WU = WUn;
                }
            }
        } else if (wid == 1) {
            // ---- stage B: WL chain, chunk k-2 (t3, t2) ----
            if (k >= 2 && k <= NCHUNK + 1) {
                const int kb = k - 2, slot = kb & 1;
                #pragma unroll 4
                for (int t = 0; t < CSTEP; ++t) {
                    const float2 rd  = sRD[slot][t][lane];
                    const float REM  = rd.x;
                    const float D1   = rd.y;
                    const float t3   = tanh_fast(REM);           // gate H(rem)
                    const float g3   = fmaf(t3,  0.5f,  0.5f);
                    const float ng3  = fmaf(t3, -0.5f, -0.5f);
                    const float aB   = REM - WL;
                    const float t2   = tanh_fast(aB);
                    const float hB   = -0.5f * aB;               // 0.5(WL-REM)
                    const float mB   = fmaf(0.5f, WL, 0.5f * REM);
                    const float ET22 = fmaf(t2, hB, mB);         // carried chain
                    const float ET2  = g3 * ET22;
                    const float WLD  = WL + D1;
                    WL = fmaf(ng3, ET22, WLD);                   // WL + D1 - ET2
                    sXD[slot][t][lane] =
                        make_float2(REM - ET2, D1 - ET2);        // (X, D2)
                }
            }
        } else if (wid == 2) {
            // ---- stage C: WD chain, chunk k-3 (t5, t4) ----
            if (k >= 3 && k <= NCHUNK + 2) {
                const int kc = k - 3, slot = kc & 1;
                #pragma unroll 4
                for (int t = 0; t < CSTEP; ++t) {
                    const float2 xd  = sXD[slot][t][lane];
                    const float X    = xd.x;
                    const float D2   = xd.y;
                    const float t5   = tanh_fast(X);             // gate H(x)
                    const float ng5  = fmaf(t5, -0.5f, -0.5f);
                    const float aC   = X - WD;
                    const float t4   = tanh_fast(aC);
                    const float hC   = -0.5f * aC;               // 0.5(WD-X)
                    const float mC   = fmaf(0.5f, WD, 0.5f * X);
                    const float ET33 = fmaf(t4, hC, mC);         // carried chain
                    const float WDD  = WD + D2;
                    const float WDn  = fmaf(ng5, ET33, WDD);     // WD + D2 - ET3
                    sWD[slot][t][lane] = WDn;
                    WD = WDn;
                }
            }
        } else if (wid == 3) {
            // ---- stage D: runoff/q + stores, chunk k-4 (tq) ----
            if (k >= 4) {
                const int kd = k - 4, slot = kd & 1, cslot = kd & 3;
                #pragma unroll
                for (int j = 0; j < NGRP_C; ++j) {
                    float qv[4];
                    #pragma unroll
                    for (int i = 0; i < 4; ++i) {
                        const int   t   = j * 4 + i;
                        const float WDn = sWD[slot][t][lane];
                        const float ct2 = sCT[cslot][t][lane];
                        const float v   = WDn * invW10;          // wd/W
                        const float bv  = negb2 * v;
                        const float dd  = fmaf(bv, v, ct2);      // p - s
                        const float tq  = tanh_fast(10.0f * dd);
                        const float qh  = halfF * dd;
                        qv[i] = fmaf(tq, qh, qh);                // F*H(p-s)*(p-s)
                    }
                    out4[kd * NGRP_C + j] =
                        make_float4(qv[0], qv[1], qv[2], qv[3]);
                }
            }
        }
        __syncthreads();
    }
}

extern "C" void kernel_launch(void* const* d_in, const int* in_sizes, int n_in,
                              void* d_out, int out_size) {
    const float* inputs = (const float*)d_in[0];
    const float* wum = (const float*)d_in[1];
    const float* wlm = (const float*)d_in[2];
    const float* wdm = (const float*)d_in[3];
    const float* c   = (const float*)d_in[4];
    const float* bb  = (const float*)d_in[5];
    const float* k1  = (const float*)d_in[6];
    const float* k2  = (const float*)d_in[7];
    const float* k3  = (const float*)d_in[8];
    float* out = (float*)d_out;

    const int B = in_sizes[0] / (T_LEN * 3);

    dim3 block(160);                // 5 warps: A, B, C, D, Loader
    dim3 grid(B / 32);              // 32 rows per block
    xaj_kernel<<<grid, block>>>(inputs, wum, wlm, wdm, c, bb, k1, k2, k3, out, B);
}